// round 12
// baseline (speedup 1.0000x reference)
#include <cuda_runtime.h>

// Fixed problem shape
#define BB   2048
#define TTN  2048
#define HH   51
#define RPB  16          // batch rows per block
#define NBLK 128
#define NTHR 256
#define GT   204         // gate threads: u=tid>>2 (0..50), rh=(tid>>1)&1, ks=tid&1

typedef unsigned long long u64;

__device__ __forceinline__ u64 pk2(float a) {
    u64 r; asm("mov.b64 %0, {%1, %1};" : "=l"(r) : "f"(a)); return r;
}
__device__ __forceinline__ u64 fma2(u64 a, u64 b, u64 c) {
    u64 d; asm("fma.rn.f32x2 %0, %1, %2, %3;" : "=l"(d) : "l"(a), "l"(b), "l"(c)); return d;
}
__device__ __forceinline__ u64 add2(u64 a, u64 b) {
    u64 d; asm("add.rn.f32x2 %0, %1, %2;" : "=l"(d) : "l"(a), "l"(b)); return d;
}
union U2 { u64 v; float2 f; };

__device__ __forceinline__ float tanhap(float x) {
    float y; asm("tanh.approx.f32 %0, %1;" : "=f"(y) : "f"(x)); return y;
}
__device__ __forceinline__ float sigap(float x) {
    return fmaf(0.5f, tanhap(0.5f * x), 0.5f);
}
__device__ __forceinline__ float cellstep(float gi, float gf, float gg, float go, float& c) {
    float cn = sigap(gf) * c + sigap(gi) * tanhap(gg);
    c = cn;
    return sigap(go) * tanhap(cn);
}

// ---------------- smem layout (float offsets) ----------------
// W1s : [k 0..51][u*4+g] row 208 fl; k<51 = Whh1[:,k], k=51 = Wih1 (x weight)
// W2s : [k 0..102][u*4+g]; k<51 = Wih2[:,k] (h1), k=51 = 0 (x slot), 52..102 = Whh2[:,k-52]
// hcat: [k 0..102][row 0..15 pad 20]; k: 0..50 h1_t, 51 x_{t+1}, 52..102 h2_{t-1}
#define W1S_OFF 0                        // 52*208 = 10816
#define W2S_OFF 10816                    // 103*208 = 21424
#define HC_OFF  32240                    // 103*20 = 2060
#define BS1_OFF 34300                    // 208
#define BS2_OFF 34508                    // 208
#define WLS_OFF 34716                    // 64
#define SM_TOT  34780                    // 139,120 B

__global__ __launch_bounds__(NTHR, 1)
void lstm2_kernel(const float* __restrict__ input,
                  const float* __restrict__ Wih1, const float* __restrict__ Whh1,
                  const float* __restrict__ bih1, const float* __restrict__ bhh1,
                  const float* __restrict__ Wih2, const float* __restrict__ Whh2,
                  const float* __restrict__ bih2, const float* __restrict__ bhh2,
                  const float* __restrict__ Wlin, const float* __restrict__ blin,
                  float* __restrict__ out)
{
    extern __shared__ float sm[];
    const int tid  = threadIdx.x;
    const int row0 = blockIdx.x * RPB;

    float*  hcf  = sm + HC_OFF;
    float*  bs1  = sm + BS1_OFF;
    float*  bs2  = sm + BS2_OFF;
    float*  wls  = sm + WLS_OFF;
    const float4* W1s4 = reinterpret_cast<const float4*>(sm + W1S_OFF);
    const float4* W2s4 = reinterpret_cast<const float4*>(sm + W2S_OFF);

    // ---------------- staging ----------------
    for (int q = tid; q < 52 * 204; q += NTHR) {
        int k = q / 204, c = q % 204;
        int uu = c >> 2, g = c & 3, j = g * HH + uu;
        sm[W1S_OFF + k * 208 + c] = (k < HH) ? Whh1[j * HH + k] : Wih1[j];
    }
    for (int q = tid; q < 103 * 204; q += NTHR) {
        int k = q / 204, c = q % 204;
        int uu = c >> 2, g = c & 3, j = g * HH + uu;
        float v;
        if (k < HH)       v = Wih2[j * HH + k];
        else if (k == HH) v = 0.0f;
        else              v = Whh2[j * HH + (k - 52)];
        sm[W2S_OFF + k * 208 + c] = v;
    }
    for (int c = tid; c < 208; c += NTHR) {
        if (c < 204) {
            int uu = c >> 2, g = c & 3, j = g * HH + uu;
            bs1[c] = bih1[j] + bhh1[j];
            bs2[c] = bih2[j] + bhh2[j];
        } else { bs1[c] = 0.f; bs2[c] = 0.f; }
    }
    if (tid < HH) wls[tid] = Wlin[tid];
    for (int i = tid; i < 103 * 20; i += NTHR) hcf[i] = 0.0f;
    __syncthreads();
    if (tid < RPB) hcf[51 * 20 + tid] = input[(row0 + tid) * TTN];   // x_0
    __syncthreads();

    // ---------------- roles ----------------
    const bool cw = (tid < GT);
    const int  u = tid >> 2, rh = (tid >> 1) & 1, ks = tid & 1;
    const int  rbase = rh * 8;            // 8-row group for GEMM h loads
    const int  arow  = rbase + ks * 4;    // 4 rows this thread owns for ACT
    const unsigned pmask = 3u << ((tid & 31) & ~1);   // shfl pair mask

    // split-K bounds
    const int kb1 = ks * 26;              // shared loop: [kb1, kb1+26)  (k 0..51)
    const int kb2 = 52 + ks * 26;         // second loop: ks=0 -> [52,78), ks=1 -> [78,103)
    const int ke2 = ks ? 103 : 78;

    const bool yw = (tid >= 204 && tid < 220);
    const int  yr = tid - 204;
    const bool xw = (tid >= 220 && tid < 228);
    const int  xi = tid - 220;

    float c1s[4] = {0,0,0,0};
    float c2s[4] = {0,0,0,0};
    U2 acc1[4][4], acc2[4][4];     // [gate][rowpair] partials (split-K)
    U2 r1[4][2],  r2[4][2];        // [gate][kept rowpair] reduced gates
    const float ybias = blin[0];

    float2 xa = make_float2(0.f, 0.f);    // x_{t+1} prefetch (2 rows per x-thread)
    if (xw) xa = make_float2(input[(row0 + 2 * xi) * TTN + 1],
                             input[(row0 + 2 * xi + 1) * TTN + 1]);

    #define GLOOP_SHARED(kv)                                                              \
        {                                                                                  \
            float4 w1 = W1s4[(kv) * 52 + u];                                               \
            float4 w2 = W2s4[(kv) * 52 + u];                                               \
            const ulonglong2* hp = reinterpret_cast<const ulonglong2*>(&hcf[(kv) * 20 + rbase]); \
            ulonglong2 hA = hp[0], hB = hp[1];                                             \
            u64 wg;                                                                        \
            wg = pk2(w1.x);                                                                \
            acc1[0][0].v = fma2(wg, hA.x, acc1[0][0].v); acc1[0][1].v = fma2(wg, hA.y, acc1[0][1].v); \
            acc1[0][2].v = fma2(wg, hB.x, acc1[0][2].v); acc1[0][3].v = fma2(wg, hB.y, acc1[0][3].v); \
            wg = pk2(w1.y);                                                                \
            acc1[1][0].v = fma2(wg, hA.x, acc1[1][0].v); acc1[1][1].v = fma2(wg, hA.y, acc1[1][1].v); \
            acc1[1][2].v = fma2(wg, hB.x, acc1[1][2].v); acc1[1][3].v = fma2(wg, hB.y, acc1[1][3].v); \
            wg = pk2(w1.z);                                                                \
            acc1[2][0].v = fma2(wg, hA.x, acc1[2][0].v); acc1[2][1].v = fma2(wg, hA.y, acc1[2][1].v); \
            acc1[2][2].v = fma2(wg, hB.x, acc1[2][2].v); acc1[2][3].v = fma2(wg, hB.y, acc1[2][3].v); \
            wg = pk2(w1.w);                                                                \
            acc1[3][0].v = fma2(wg, hA.x, acc1[3][0].v); acc1[3][1].v = fma2(wg, hA.y, acc1[3][1].v); \
            acc1[3][2].v = fma2(wg, hB.x, acc1[3][2].v); acc1[3][3].v = fma2(wg, hB.y, acc1[3][3].v); \
            wg = pk2(w2.x);                                                                \
            acc2[0][0].v = fma2(wg, hA.x, acc2[0][0].v); acc2[0][1].v = fma2(wg, hA.y, acc2[0][1].v); \
            acc2[0][2].v = fma2(wg, hB.x, acc2[0][2].v); acc2[0][3].v = fma2(wg, hB.y, acc2[0][3].v); \
            wg = pk2(w2.y);                                                                \
            acc2[1][0].v = fma2(wg, hA.x, acc2[1][0].v); acc2[1][1].v = fma2(wg, hA.y, acc2[1][1].v); \
            acc2[1][2].v = fma2(wg, hB.x, acc2[1][2].v); acc2[1][3].v = fma2(wg, hB.y, acc2[1][3].v); \
            wg = pk2(w2.z);                                                                \
            acc2[2][0].v = fma2(wg, hA.x, acc2[2][0].v); acc2[2][1].v = fma2(wg, hA.y, acc2[2][1].v); \
            acc2[2][2].v = fma2(wg, hB.x, acc2[2][2].v); acc2[2][3].v = fma2(wg, hB.y, acc2[2][3].v); \
            wg = pk2(w2.w);                                                                \
            acc2[3][0].v = fma2(wg, hA.x, acc2[3][0].v); acc2[3][1].v = fma2(wg, hA.y, acc2[3][1].v); \
            acc2[3][2].v = fma2(wg, hB.x, acc2[3][2].v); acc2[3][3].v = fma2(wg, hB.y, acc2[3][3].v); \
        }

    #define GLOOP_W2ONLY(kv)                                                              \
        {                                                                                  \
            float4 w2 = W2s4[(kv) * 52 + u];                                               \
            const ulonglong2* hp = reinterpret_cast<const ulonglong2*>(&hcf[(kv) * 20 + rbase]); \
            ulonglong2 hA = hp[0], hB = hp[1];                                             \
            u64 wg;                                                                        \
            wg = pk2(w2.x);                                                                \
            acc2[0][0].v = fma2(wg, hA.x, acc2[0][0].v); acc2[0][1].v = fma2(wg, hA.y, acc2[0][1].v); \
            acc2[0][2].v = fma2(wg, hB.x, acc2[0][2].v); acc2[0][3].v = fma2(wg, hB.y, acc2[0][3].v); \
            wg = pk2(w2.y);                                                                \
            acc2[1][0].v = fma2(wg, hA.x, acc2[1][0].v); acc2[1][1].v = fma2(wg, hA.y, acc2[1][1].v); \
            acc2[1][2].v = fma2(wg, hB.x, acc2[1][2].v); acc2[1][3].v = fma2(wg, hB.y, acc2[1][3].v); \
            wg = pk2(w2.z);                                                                \
            acc2[2][0].v = fma2(wg, hA.x, acc2[2][0].v); acc2[2][1].v = fma2(wg, hA.y, acc2[2][1].v); \
            acc2[2][2].v = fma2(wg, hB.x, acc2[2][2].v); acc2[2][3].v = fma2(wg, hB.y, acc2[2][3].v); \
            wg = pk2(w2.w);                                                                \
            acc2[3][0].v = fma2(wg, hA.x, acc2[3][0].v); acc2[3][1].v = fma2(wg, hA.y, acc2[3][1].v); \
            acc2[3][2].v = fma2(wg, hB.x, acc2[3][2].v); acc2[3][3].v = fma2(wg, hB.y, acc2[3][3].v); \
        }

    // pairwise split-K reduction: ks=0 keeps rowpairs {0,1}; ks=1 keeps {2,3}
    #define REDUCE(accX, rX)                                                              \
        _Pragma("unroll")                                                                  \
        for (int g = 0; g < 4; g++) {                                                      \
            _Pragma("unroll")                                                              \
            for (int j = 0; j < 2; j++) {                                                  \
                u64 send = ks ? accX[g][j].v     : accX[g][2 + j].v;                       \
                u64 keep = ks ? accX[g][2 + j].v : accX[g][j].v;                           \
                u64 recv = __shfl_xor_sync(pmask, send, 1);                                \
                rX[g][j].v = add2(keep, recv);                                             \
            }                                                                              \
        }

    // ---------------- prolog: L1 gates for t=0 (h1=0, x_0) ----------------
    if (cw) {
        #pragma unroll
        for (int g = 0; g < 4; g++) {
            u64 b = ks ? 0ull : pk2(bs1[u * 4 + g]);
            acc1[g][0].v = b; acc1[g][1].v = b; acc1[g][2].v = b; acc1[g][3].v = b;
            acc2[g][0].v = 0ull; acc2[g][1].v = 0ull; acc2[g][2].v = 0ull; acc2[g][3].v = 0ull;
        }
        #pragma unroll 4
        for (int k = kb1; k < kb1 + 26; k++) GLOOP_SHARED(k)
        REDUCE(acc1, r1)
    }
    __syncthreads();

    // ---------------- main loop: 2 barriers/step ----------------
    for (int t = 0; t < TTN; t++) {
        // === ACT: act1(r1)->h1_t; act2(r2)->h2_{t-1}; publish x_{t+1} ===
        if (cw) {
            float h1n[4];
            #pragma unroll
            for (int j = 0; j < 2; j++) {
                float2 gi = r1[0][j].f, gf = r1[1][j].f, gG = r1[2][j].f, go = r1[3][j].f;
                h1n[2*j]   = cellstep(gi.x, gf.x, gG.x, go.x, c1s[2*j]);
                h1n[2*j+1] = cellstep(gi.y, gf.y, gG.y, go.y, c1s[2*j+1]);
            }
            *reinterpret_cast<float4*>(&hcf[u * 20 + arow]) = make_float4(h1n[0], h1n[1], h1n[2], h1n[3]);
            if (t > 0) {
                float h2n[4];
                #pragma unroll
                for (int j = 0; j < 2; j++) {
                    float2 gi = r2[0][j].f, gf = r2[1][j].f, gG = r2[2][j].f, go = r2[3][j].f;
                    h2n[2*j]   = cellstep(gi.x, gf.x, gG.x, go.x, c2s[2*j]);
                    h2n[2*j+1] = cellstep(gi.y, gf.y, gG.y, go.y, c2s[2*j+1]);
                }
                *reinterpret_cast<float4*>(&hcf[(52 + u) * 20 + arow]) = make_float4(h2n[0], h2n[1], h2n[2], h2n[3]);
            }
        } else if (xw && t + 1 < TTN) {
            hcf[51 * 20 + 2 * xi]     = xa.x;           // publish x_{t+1}
            hcf[51 * 20 + 2 * xi + 1] = xa.y;
            if (t + 2 < TTN)
                xa = make_float2(input[(row0 + 2 * xi) * TTN + t + 2],
                                 input[(row0 + 2 * xi + 1) * TTN + t + 2]);
        }
        __syncthreads();

        // === GEMM: acc2 = W2*[h1_t, h2_{t-1}]; acc1 = W1*[h1_t, x_{t+1}]; reduce ===
        if (cw) {
            #pragma unroll
            for (int g = 0; g < 4; g++) {
                u64 b1 = ks ? 0ull : pk2(bs1[u * 4 + g]);
                u64 b2 = ks ? 0ull : pk2(bs2[u * 4 + g]);
                acc1[g][0].v = b1; acc1[g][1].v = b1; acc1[g][2].v = b1; acc1[g][3].v = b1;
                acc2[g][0].v = b2; acc2[g][1].v = b2; acc2[g][2].v = b2; acc2[g][3].v = b2;
            }
            #pragma unroll 4
            for (int k = kb1; k < kb1 + 26; k++) GLOOP_SHARED(k)      // h1 + x slot
            #pragma unroll 4
            for (int k = kb2; k < ke2; k++) GLOOP_W2ONLY(k)           // h2_{t-1}
            REDUCE(acc1, r1)
            REDUCE(acc2, r2)
        } else if (yw && t > 0) {
            // y_{t-1} from h2_{t-1} (stable during GEMM)
            float y = ybias;
            #pragma unroll 3
            for (int k = 0; k < HH; k++)
                y += hcf[(52 + k) * 20 + yr] * wls[k];
            out[(row0 + yr) * TTN + (t - 1)] = y;
        }
        __syncthreads();
    }

    // ---------------- epilog: act2 for t=TTN-1, then y_{TTN-1} ----------------
    if (cw) {
        float h2n[4];
        #pragma unroll
        for (int j = 0; j < 2; j++) {
            float2 gi = r2[0][j].f, gf = r2[1][j].f, gG = r2[2][j].f, go = r2[3][j].f;
            h2n[2*j]   = cellstep(gi.x, gf.x, gG.x, go.x, c2s[2*j]);
            h2n[2*j+1] = cellstep(gi.y, gf.y, gG.y, go.y, c2s[2*j+1]);
        }
        *reinterpret_cast<float4*>(&hcf[(52 + u) * 20 + arow]) = make_float4(h2n[0], h2n[1], h2n[2], h2n[3]);
    }
    __syncthreads();
    if (yw) {
        float y = ybias;
        #pragma unroll 3
        for (int k = 0; k < HH; k++)
            y += hcf[(52 + k) * 20 + yr] * wls[k];
        out[(row0 + yr) * TTN + (TTN - 1)] = y;
    }
}

extern "C" void kernel_launch(void* const* d_in, const int* in_sizes, int n_in,
                              void* d_out, int out_size) {
    const float* input = (const float*)d_in[0];
    const float* Wih1  = (const float*)d_in[1];
    const float* Whh1  = (const float*)d_in[2];
    const float* bih1  = (const float*)d_in[3];
    const float* bhh1  = (const float*)d_in[4];
    const float* Wih2  = (const float*)d_in[5];
    const float* Whh2  = (const float*)d_in[6];
    const float* bih2  = (const float*)d_in[7];
    const float* bhh2  = (const float*)d_in[8];
    const float* Wlin  = (const float*)d_in[9];
    const float* blin  = (const float*)d_in[10];
    float* out = (float*)d_out;

    const size_t smem = SM_TOT * sizeof(float);   // ~139 KB
    cudaFuncSetAttribute(lstm2_kernel, cudaFuncAttributeMaxDynamicSharedMemorySize, (int)smem);

    lstm2_kernel<<<NBLK, NTHR, smem>>>(input, Wih1, Whh1, bih1, bhh1,
                                       Wih2, Whh2, bih2, bhh2, Wlin, blin, out);
}